// round 8
// baseline (speedup 1.0000x reference)
#include <cuda_runtime.h>
#include <cuda_fp16.h>
#include <cstdint>

#define E_      8
#define D_      512
#define TMAX    32768
#define MAXTILES 264

// ---------------- scratch (allocation-free __device__ globals) ----------------
__device__ int g_cursor[E_];
__device__ int g_counts[E_];
__device__ int g_bucket[E_ * TMAX];
__device__ int g_tile_e[MAXTILES];
__device__ int g_tile_m[MAXTILES];
__device__ int g_num_tiles;

__device__ __align__(16) __half g_Xh[(size_t)TMAX * D_];
__device__ __align__(16) __half g_Wh[(size_t)E_ * D_ * D_];

// ---------------- helpers ----------------
__device__ __forceinline__ uint32_t smem_u32(const void* p) {
    uint32_t a;
    asm("{ .reg .u64 t; cvta.to.shared.u64 t, %1; cvt.u32.u64 %0, t; }" : "=r"(a) : "l"(p));
    return a;
}

#define CP16(d, s) asm volatile("cp.async.cg.shared.global [%0], [%1], 16;" :: "r"(d), "l"(s) : "memory")

#define LDSM4(r, a)                                                                  \
    asm volatile("ldmatrix.sync.aligned.m8n8.x4.shared.b16 {%0,%1,%2,%3}, [%4];"     \
        : "=r"((r)[0]), "=r"((r)[1]), "=r"((r)[2]), "=r"((r)[3]) : "r"(a))

#define MMA(c, a, b)                                                                 \
    asm volatile("mma.sync.aligned.m16n8k16.row.col.f32.f16.f16.f32 "                \
        "{%0,%1,%2,%3},{%4,%5,%6,%7},{%8,%9},{%0,%1,%2,%3};"                         \
        : "+f"((c)[0]), "+f"((c)[1]), "+f"((c)[2]), "+f"((c)[3])                     \
        : "r"((a)[0]), "r"((a)[1]), "r"((a)[2]), "r"((a)[3]),                        \
          "r"((b)[0]), "r"((b)[1]))

// ---------------- prep: convert W to fp16 + zero cursors ----------------
__global__ void k_prep(const float* __restrict__ W) {
    if (blockIdx.x == 0 && threadIdx.x < E_) g_cursor[threadIdx.x] = 0;
    size_t i = (size_t)blockIdx.x * blockDim.x + threadIdx.x;
    float4 v0 = ((const float4*)W)[2 * i];
    float4 v1 = ((const float4*)W)[2 * i + 1];
    __half2 h0 = __floats2half2_rn(v0.x, v0.y);
    __half2 h1 = __floats2half2_rn(v0.z, v0.w);
    __half2 h2 = __floats2half2_rn(v1.x, v1.y);
    __half2 h3 = __floats2half2_rn(v1.z, v1.w);
    uint4 o;
    o.x = *(uint32_t*)&h0; o.y = *(uint32_t*)&h1;
    o.z = *(uint32_t*)&h2; o.w = *(uint32_t*)&h3;
    ((uint4*)g_Wh)[i] = o;
}

__global__ void k_convx(const float* __restrict__ x) {
    size_t i = (size_t)blockIdx.x * blockDim.x + threadIdx.x;
    float4 v0 = ((const float4*)x)[2 * i];
    float4 v1 = ((const float4*)x)[2 * i + 1];
    __half2 h0 = __floats2half2_rn(v0.x, v0.y);
    __half2 h1 = __floats2half2_rn(v0.z, v0.w);
    __half2 h2 = __floats2half2_rn(v1.x, v1.y);
    __half2 h3 = __floats2half2_rn(v1.z, v1.w);
    uint4 o;
    o.x = *(uint32_t*)&h0; o.y = *(uint32_t*)&h1;
    o.z = *(uint32_t*)&h2; o.w = *(uint32_t*)&h3;
    ((uint4*)g_Xh)[i] = o;
}

// ---------------- direct scatter into per-expert buckets ----------------
__global__ void k_scat(const int* __restrict__ p, int T) {
    __shared__ int s_cnt[E_], s_base[E_];
    if (threadIdx.x < E_) s_cnt[threadIdx.x] = 0;
    __syncthreads();
    int t = blockIdx.x * blockDim.x + threadIdx.x;
    int e = 0, rank = 0;
    if (t < T) { e = p[t]; rank = atomicAdd(&s_cnt[e], 1); }
    __syncthreads();
    if (threadIdx.x < E_ && s_cnt[threadIdx.x])
        s_base[threadIdx.x] = atomicAdd(&g_cursor[threadIdx.x], s_cnt[threadIdx.x]);
    __syncthreads();
    if (t < T) g_bucket[e * TMAX + s_base[e] + rank] = t;
}

__global__ void k_tiles() {
    if (threadIdx.x == 0) {
        int nt = 0;
        for (int e = 0; e < E_; e++) {
            int c = g_cursor[e];
            g_counts[e] = c;
            int mt = (c + 127) >> 7;
            for (int m = 0; m < mt; m++) { g_tile_e[nt] = e; g_tile_m[nt] = m; nt++; }
        }
        g_num_tiles = nt;
    }
}

// ---------------- grouped GEMM: FP16 HMMA, 64x64 warp tiles ----------------
// CTA 128(M) x 128(N), 128 threads = 4 warps (2x2), warp tile 64x64.
// K=512 in 16 chunks of 32. SMEM tile: 128 rows x 64B fp16, XOR swizzle
// c' = c ^ ((row>>1)&3). Both operands via cp.async, 4-stage ring.
#define OFF_A       0
#define OFF_W       8192
#define STG         16384
#define NST         4
#define SMEM_GEMM   (1024 + NST * STG)

__global__ void __launch_bounds__(128, 2)
k_gemm(const float* __restrict__ bias, float* __restrict__ out) {
    extern __shared__ unsigned char smem[];
    const int ti = blockIdx.y;
    if (ti >= g_num_tiles) return;
    const int nt    = blockIdx.x;
    const int e     = g_tile_e[ti];
    const int mtile = g_tile_m[ti];
    const int count = g_counts[e];

    int* rows = (int*)smem;
    const int tid = threadIdx.x, lane = tid & 31, wid = tid >> 5;

    {
        int m = mtile * 128 + tid;
        rows[tid] = (m < count) ? g_bucket[e * TMAX + m] : -1;
    }
    __syncthreads();

    // ---- loader: one full 64B row per thread per kc ----
    const int lrow = tid;
    int tokA = rows[lrow]; if (tokA < 0) tokA = 0;
    const char* srcA = (const char*)(g_Xh + (size_t)tokA * D_);
    const char* srcW = (const char*)(g_Wh + ((size_t)e * D_ + (size_t)(nt * 128 + lrow)) * D_);

    const uint32_t sb = smem_u32(smem) + 1024;
    const uint32_t sw_ = (uint32_t)((lrow >> 1) & 3);
    const uint32_t dR = (uint32_t)lrow * 64;
    uint32_t dc[4];
    #pragma unroll
    for (int c = 0; c < 4; c++) dc[c] = dR + (((uint32_t)c ^ sw_) * 16);

    #define LOAD_STAGE(st, kc) do {                                                  \
        uint32_t b_ = sb + (uint32_t)(st) * STG;                                      \
        const char* sa_ = srcA + (size_t)(kc) * 64;                                   \
        const char* sw2_ = srcW + (size_t)(kc) * 64;                                  \
        _Pragma("unroll")                                                            \
        for (int c = 0; c < 4; c++) {                                                \
            CP16(b_ + OFF_A + dc[c], sa_ + c * 16);                                   \
            CP16(b_ + OFF_W + dc[c], sw2_ + c * 16);                                  \
        }                                                                            \
        asm volatile("cp.async.commit_group;" ::: "memory");                          \
    } while (0)

    // ---- mma fragment addressing: warp tile 64x64 ----
    const int m0 = (wid & 1) * 64;
    const int n0 = (wid >> 1) * 64;
    const uint32_t hA = (uint32_t)((lane >> 4) & 1);
    uint32_t aoff[4];   // 4 m16 blocks
    uint32_t sAv[4];
    #pragma unroll
    for (int ma = 0; ma < 4; ma++) {
        uint32_t rA = (uint32_t)(m0 + ma * 16 + (lane & 15));
        sAv[ma] = (rA >> 1) & 3;
        aoff[ma] = rA * 64;
    }
    const uint32_t rB0 = (uint32_t)(n0 + ((lane >> 4) & 1) * 8 + (lane & 7));
    const uint32_t hB  = (uint32_t)((lane >> 3) & 1);
    const uint32_t sB  = (rB0 >> 1) & 3;
    const uint32_t rowB = rB0 * 64;

    float acc[4][8][4];
    #pragma unroll
    for (int i = 0; i < 4; i++)
        #pragma unroll
        for (int j = 0; j < 8; j++)
            #pragma unroll
            for (int q = 0; q < 4; q++) acc[i][j][q] = 0.f;

    LOAD_STAGE(0, 0);
    LOAD_STAGE(1, 1);
    LOAD_STAGE(2, 2);

    for (int kc = 0; kc < 16; kc++) {
        if (kc < 14)       asm volatile("cp.async.wait_group 2;" ::: "memory");
        else if (kc == 14) asm volatile("cp.async.wait_group 1;" ::: "memory");
        else               asm volatile("cp.async.wait_group 0;" ::: "memory");
        __syncthreads();
        if (kc + 3 < 16) LOAD_STAGE((kc + 3) & 3, kc + 3);

        const uint32_t stb = sb + (uint32_t)(kc & 3) * STG;

        #pragma unroll
        for (int ks = 0; ks < 2; ks++) {
            uint32_t a[4][4];
            #pragma unroll
            for (int ma = 0; ma < 4; ma++) {
                const uint32_t ca = (((uint32_t)(2 * ks) + hA) ^ sAv[ma]) * 16;
                LDSM4(a[ma], stb + OFF_A + aoff[ma] + ca);
            }
            const uint32_t cb = (((uint32_t)(2 * ks) + hB) ^ sB) * 16;
            #pragma unroll
            for (int pp = 0; pp < 4; pp++) {
                uint32_t bw[4];
                LDSM4(bw, stb + OFF_W + rowB + (uint32_t)pp * 1024 + cb);
                #pragma unroll
                for (int ma = 0; ma < 4; ma++) {
                    MMA(acc[ma][2 * pp],     a[ma], (bw + 0));
                    MMA(acc[ma][2 * pp + 1], a[ma], (bw + 2));
                }
            }
        }
    }

    // ---- epilogue: bias + scatter by token ----
    const int gid = lane >> 2, tig = lane & 3;
    const int ncol0 = nt * 128 + n0 + 2 * tig;
    float2 bv[8];
    #pragma unroll
    for (int nb = 0; nb < 8; nb++)
        bv[nb] = *(const float2*)(bias + e * D_ + ncol0 + nb * 8);

    #pragma unroll
    for (int ma = 0; ma < 4; ma++) {
        #pragma unroll
        for (int h = 0; h < 2; h++) {
            int m = m0 + ma * 16 + h * 8 + gid;
            int tok = rows[m];
            if (tok < 0) continue;
            float* orow = out + (size_t)tok * D_ + ncol0;
            #pragma unroll
            for (int nb = 0; nb < 8; nb++) {
                float2 o;
                o.x = acc[ma][nb][2 * h]     + bv[nb].x;
                o.y = acc[ma][nb][2 * h + 1] + bv[nb].y;
                *(float2*)(orow + nb * 8) = o;
            }
        }
    }
}

// ---------------- launch ----------------
extern "C" void kernel_launch(void* const* d_in, const int* in_sizes, int n_in,
                              void* d_out, int out_size) {
    const float* x = (const float*)d_in[0];
    const int*   p = (const int*)d_in[1];
    const float* W = (const float*)d_in[2];
    const float* b = (const float*)d_in[3];
    float* out = (float*)d_out;
    const int T = in_sizes[1];

    static bool attr_done = false;
    if (!attr_done) {
        cudaFuncSetAttribute(k_gemm, cudaFuncAttributeMaxDynamicSharedMemorySize, SMEM_GEMM);
        attr_done = true;
    }

    k_prep<<<(E_ * D_ * D_ / 8) / 256, 256>>>(W);
    k_convx<<<(TMAX * D_ / 8) / 256, 256>>>(x);
    k_scat<<<(T + 255) / 256, 256>>>(p, T);
    k_tiles<<<1, 32>>>();

    dim3 grid(4, MAXTILES, 1);
    k_gemm<<<grid, 128, SMEM_GEMM>>>(b, out);
}